// round 2
// baseline (speedup 1.0000x reference)
#include <cuda_runtime.h>
#include <math.h>

#define NN    4096
#define RR    4
#define FINN  128
#define HH    64
#define CC    16
#define LLAY  2
#define TT    512
#define ELL_S 128   // max nnz/row (mean ~21.5, sigma ~4.5 -> huge margin)
#define NH    (NN*HH)

// cos(2*pi*k*r/4) — real-part DFT matrix for length-4 FFT. Rows/cols 1 and 3 identical.
__device__ __constant__ float Mc[4][4] = {
  { 1.f,  1.f,  1.f,  1.f},
  { 1.f,  0.f, -1.f,  0.f},
  { 1.f, -1.f,  1.f, -1.f},
  { 1.f,  0.f, -1.f,  0.f}
};

// ---- static scratch ----
__device__ float g_d   [RR*NN];           // D^-1/2 per (relation,row)
__device__ int   g_cnt [RR*NN];
__device__ int   g_cols[RR*NN*ELL_S];     // ELL column indices
__device__ float g_dw  [RR*NN*ELL_S];     // d_j per slot (for spmm3)
__device__ float g_Y   [RR*NN*HH];        // dense GEMM out, pre-scaled by d_j
__device__ float g_h   [RR*NN*HH];        // GCN hidden, plane layout [r][j][h]
__device__ float g_tX  [NN*HH*RR];        // interleaved [i][h][r] (head input)
__device__ float g_XhatP[3*NN*HH];        // frequency planes [k][j][h]
__device__ float4 g_O4 [NN*HH];           // Ohat interleaved {k0,k1,k2,pad}
__device__ float g_What[LLAY*3*HH*HH];
__device__ float g_losses[TT];
__device__ float g_yscratch[TT*CC];

// ------------------------------------------------------------------
// K1: single dense pass over A -> ELL pattern + degrees. Warp per row,
// float4 loads, ordered compaction via 4 ballots (lane-major j order).
// ------------------------------------------------------------------
__global__ void k_build(const float* __restrict__ A) {
    int warp = (blockIdx.x * blockDim.x + threadIdx.x) >> 5;
    int lane = threadIdx.x & 31;
    if (warp >= RR * NN) return;
    int i = warp & (NN - 1);
    const float4* row4 = (const float4*)(A + (size_t)warp * NN);
    int* crow = g_cols + (size_t)warp * ELL_S;
    unsigned bm = (1u << lane) - 1u;
    int cnt = 0;
    #pragma unroll 2
    for (int it = 0; it < NN / 128; it++) {
        float4 v = row4[it * 32 + lane];
        int jb = it * 128 + lane * 4;
        bool n0 = (v.x != 0.f) || (jb     == i);
        bool n1 = (v.y != 0.f) || (jb + 1 == i);
        bool n2 = (v.z != 0.f) || (jb + 2 == i);
        bool n3 = (v.w != 0.f) || (jb + 3 == i);
        unsigned m0 = __ballot_sync(0xffffffffu, n0);
        unsigned m1 = __ballot_sync(0xffffffffu, n1);
        unsigned m2 = __ballot_sync(0xffffffffu, n2);
        unsigned m3 = __ballot_sync(0xffffffffu, n3);
        int p = cnt + __popc(m0 & bm) + __popc(m1 & bm) + __popc(m2 & bm) + __popc(m3 & bm);
        if (n0) { if (p < ELL_S) crow[p] = jb;     p++; }
        if (n1) { if (p < ELL_S) crow[p] = jb + 1; p++; }
        if (n2) { if (p < ELL_S) crow[p] = jb + 2; p++; }
        if (n3) { if (p < ELL_S) crow[p] = jb + 3; p++; }
        cnt += __popc(m0) + __popc(m1) + __popc(m2) + __popc(m3);
    }
    if (cnt > ELL_S) cnt = ELL_S;
    if (lane == 0) {
        g_cnt[warp] = cnt;
        g_d[warp] = rsqrtf((float)cnt);   // rowsum == cnt (entries are exactly 1.0), cnt>=1
    }
}

// K1b: dw[row][s] = d[r, col]  (needs all of g_d -> separate kernel)
__global__ void k_fill_dw() {
    int row = (blockIdx.x * blockDim.x + threadIdx.x) >> 5;
    int lane = threadIdx.x & 31;
    if (row >= RR * NN) return;
    int rbase = row & ~(NN - 1);
    int cnt = g_cnt[row];
    const int* crow = g_cols + (size_t)row * ELL_S;
    float* dwr = g_dw + (size_t)row * ELL_S;
    for (int s = lane; s < cnt; s += 32) dwr[s] = g_d[rbase + crow[s]];
}

// Precompute both layers' frequency-domain weights.
__global__ void k_what_all(const float* __restrict__ W) {
    int idx = blockIdx.x * blockDim.x + threadIdx.x;
    if (idx >= LLAY * HH * HH) return;
    int l = idx / (HH * HH), q = idx % (HH * HH);
    const float* p = W + (size_t)idx * RR;
    float w0 = p[0], w1 = p[1], w2 = p[2], w3 = p[3];
    float* base = g_What + (size_t)l * 3 * HH * HH;
    base[q]               = w0 + w1 + w2 + w3;
    base[HH*HH + q]       = w0 - w2;
    base[2*HH*HH + q]     = w0 - w1 + w2 - w3;
}

// K2: Y[r,j,:] = d_rj * (X[j,:] @ W1[r]).  64 rows/block, W cached in smem.
__global__ void k_xw1(const float* __restrict__ X, const float* __restrict__ W1) {
    extern __shared__ float dsm[];
    float* sW = dsm;                 // FINN*HH
    float* sX = dsm + FINN * HH;     // 64*FINN
    int r = blockIdx.y, i0 = blockIdx.x * 64, tid = threadIdx.x;
    const float* wg = W1 + (size_t)r * FINN * HH;
    for (int q = tid; q < FINN * HH; q += 256) sW[q] = wg[q];
    for (int q = tid; q < 64 * FINN; q += 256)
        sX[q] = X[(size_t)(i0 + (q >> 7)) * FINN + (q & 127)];
    __syncthreads();
    int h = tid & 63, rg = tid >> 6;
    const float* sXb = sX + rg * 16 * FINN;
    float acc[16];
    #pragma unroll
    for (int rr = 0; rr < 16; rr++) acc[rr] = 0.f;
    for (int f = 0; f < FINN; f += 4) {
        float w0 = sW[f*64+h], w1 = sW[(f+1)*64+h], w2 = sW[(f+2)*64+h], w3 = sW[(f+3)*64+h];
        #pragma unroll
        for (int rr = 0; rr < 16; rr++) {
            float4 x = *(const float4*)&sXb[rr * FINN + f];
            acc[rr] += x.x*w0 + x.y*w1 + x.z*w2 + x.w*w3;
        }
    }
    #pragma unroll
    for (int rr = 0; rr < 16; rr++) {
        int j = i0 + rg * 16 + rr;
        int gi = (r << 12) + j;
        g_Y[(size_t)gi * HH + h] = g_d[gi] * acc[rr];
    }
}

// K4a: Y[r,j,:] = d_rj * (h[r,j,:] @ W2[r]).  64 rows/block.
__global__ void k_hw2(const float* __restrict__ W2) {
    __shared__ float sW[HH * HH];
    __shared__ float sX[64 * HH];
    int r = blockIdx.y, i0 = blockIdx.x * 64, tid = threadIdx.x;
    const float* wg = W2 + (size_t)r * HH * HH;
    for (int q = tid; q < HH * HH; q += 256) sW[q] = wg[q];
    for (int q = tid; q < 64 * HH; q += 256)
        sX[q] = g_h[((size_t)(r << 12) + i0 + (q >> 6)) * HH + (q & 63)];
    __syncthreads();
    int h = tid & 63, rg = tid >> 6;
    const float* sXb = sX + rg * 16 * HH;
    float acc[16];
    #pragma unroll
    for (int rr = 0; rr < 16; rr++) acc[rr] = 0.f;
    for (int f = 0; f < HH; f += 4) {
        float w0 = sW[f*64+h], w1 = sW[(f+1)*64+h], w2 = sW[(f+2)*64+h], w3 = sW[(f+3)*64+h];
        #pragma unroll
        for (int rr = 0; rr < 16; rr++) {
            float4 x = *(const float4*)&sXb[rr * HH + f];
            acc[rr] += x.x*w0 + x.y*w1 + x.z*w2 + x.w*w3;
        }
    }
    #pragma unroll
    for (int rr = 0; rr < 16; rr++) {
        int gi = (r << 12) + i0 + rg * 16 + rr;
        g_Y[(size_t)gi * HH + h] = g_d[gi] * acc[rr];
    }
}

// K3/K4b: h[r,i,:] = relu(d_ri * sum_{j in nnz} Y'[r,j,:] + bias[r,:])
// Y' pre-scaled by d_j. 4 rows per 256-thread block. Plane-layout output.
__global__ void k_spmm_gcn(const float* __restrict__ bias) {
    int row = blockIdx.x * 4 + (threadIdx.x >> 6);
    int h = threadIdx.x & 63;
    int r = row >> 12;
    int cnt = g_cnt[row];
    const int* crow = g_cols + (size_t)row * ELL_S;
    const float* Yb = g_Y + ((size_t)r << 12) * HH;
    float acc = 0.f;
    int s = 0;
    for (; s + 4 <= cnt; s += 4) {
        int j0 = crow[s], j1 = crow[s+1], j2 = crow[s+2], j3 = crow[s+3];
        acc += Yb[(size_t)j0*HH+h] + Yb[(size_t)j1*HH+h]
             + Yb[(size_t)j2*HH+h] + Yb[(size_t)j3*HH+h];
    }
    for (; s < cnt; s++) acc += Yb[(size_t)crow[s]*HH+h];
    float v = g_d[row] * acc + bias[r * HH + h];
    g_h[(size_t)row * HH + h] = v > 0.f ? v : 0.f;
}

// Xhat planes directly from GCN hidden planes: Xhat_k[j,h] = sum_r M[k,r] h[r,j,h]
__global__ void k_xhat() {
    int idx = blockIdx.x * blockDim.x + threadIdx.x;
    if (idx >= NH) return;
    float x0 = g_h[idx], x1 = g_h[NH + idx], x2 = g_h[2*NH + idx], x3 = g_h[3*NH + idx];
    g_XhatP[idx]        = x0 + x1 + x2 + x3;
    g_XhatP[NH + idx]   = x0 - x2;
    g_XhatP[2*NH + idx] = x0 - x1 + x2 - x3;
}

// Chat_k[i,h] = sum_r M[k,r] * d_ri * sum_{j} d_rj * Xhat_k[j,h]  (skip M==0 terms)
// then fused Ohat epilogue: O1_r = ifft.real, Ohat_k = fft(O1).real; write float4.
__global__ void k_spmm3() {
    int i = blockIdx.x;
    int tid = threadIdx.x;          // 192 threads
    int h = tid & 63, k = tid >> 6; // k = 0..2
    const float* Xp = g_XhatP + (size_t)k * NH;
    float acc = 0.f;
    #pragma unroll
    for (int r = 0; r < RR; r++) {
        float coef = Mc[k][r];
        if (coef != 0.f) {
            int row = (r << 12) + i;
            int cnt = g_cnt[row];
            const int*   crow = g_cols + (size_t)row * ELL_S;
            const float* dwr  = g_dw   + (size_t)row * ELL_S;
            float s = 0.f;
            int ss = 0;
            for (; ss + 4 <= cnt; ss += 4) {
                int j0 = crow[ss], j1 = crow[ss+1], j2 = crow[ss+2], j3 = crow[ss+3];
                float w0 = dwr[ss], w1 = dwr[ss+1], w2 = dwr[ss+2], w3 = dwr[ss+3];
                s += w0 * Xp[(size_t)j0*HH+h] + w1 * Xp[(size_t)j1*HH+h]
                   + w2 * Xp[(size_t)j2*HH+h] + w3 * Xp[(size_t)j3*HH+h];
            }
            for (; ss < cnt; ss++) s += dwr[ss] * Xp[(size_t)crow[ss]*HH+h];
            acc += coef * g_d[row] * s;
        }
    }
    __shared__ float sc[3][HH];
    sc[k][h] = acc;
    __syncthreads();
    if (tid < HH) {
        float C0 = sc[0][tid], C1 = sc[1][tid], C2 = sc[2][tid];
        // O1_r = 0.25*(C0 + 2*Mc[r][1]*C1 + Mc[r][2]*C2); Ohat_k = sum_r Mc[k][r]*O1_r
        float O0 = 0.25f * (C0 + 2.f*C1 + C2);
        float O1 = 0.25f * (C0 - C2);
        float O2 = 0.25f * (C0 - 2.f*C1 + C2);
        float O3 = O1;
        float4 o;
        o.x = O0 + O1 + O2 + O3;
        o.y = O0 - O2;
        o.z = O0 - O1 + O2 - O3;
        o.w = 0.f;
        g_O4[(size_t)i * HH + tid] = o;
    }
}

// Dhat_k = Ohat_k @ What_k ; fused epilogue: O2_r = ifft.real, relu, and
// (a) interleaved tX for the head, (b) Xhat planes for the next layer.
__global__ void k_dhat(int layer, int write_next) {
    extern __shared__ float dsm[];
    float*  sW = dsm;                          // 3*HH*HH floats
    float4* sO = (float4*)(dsm + 3 * HH * HH); // 32*HH float4
    int i0 = blockIdx.x * 32, tid = threadIdx.x;
    const float* wb = g_What + (size_t)layer * 3 * HH * HH;
    for (int q = tid; q < 3 * HH * HH; q += 256) sW[q] = wb[q];
    for (int q = tid; q < 32 * HH; q += 256)
        sO[q] = g_O4[(size_t)(i0 + (q >> 6)) * HH + (q & 63)];
    __syncthreads();
    int l = tid & 63, rg = tid >> 6;
    float a0[8], a1[8], a2[8];
    #pragma unroll
    for (int rr = 0; rr < 8; rr++) { a0[rr] = 0.f; a1[rr] = 0.f; a2[rr] = 0.f; }
    #pragma unroll 4
    for (int j = 0; j < HH; j++) {
        float w0 = sW[j*64+l], w1 = sW[HH*HH + j*64+l], w2 = sW[2*HH*HH + j*64+l];
        #pragma unroll
        for (int rr = 0; rr < 8; rr++) {
            float4 o = sO[(rg * 8 + rr) * HH + j];
            a0[rr] += o.x * w0; a1[rr] += o.y * w1; a2[rr] += o.z * w2;
        }
    }
    #pragma unroll
    for (int rr = 0; rr < 8; rr++) {
        float D0 = a0[rr], D1 = a1[rr], D2 = a2[rr];
        float v0 = 0.25f * (D0 + 2.f*D1 + D2);
        float v1 = 0.25f * (D0 - D2);
        float v2 = 0.25f * (D0 - 2.f*D1 + D2);
        float v3 = v1;
        v0 = v0 > 0.f ? v0 : 0.f;  v1 = v1 > 0.f ? v1 : 0.f;
        v2 = v2 > 0.f ? v2 : 0.f;  v3 = v3 > 0.f ? v3 : 0.f;
        int idx = (i0 + rg * 8 + rr) * HH + l;
        float4 t; t.x = v0; t.y = v1; t.z = v2; t.w = v3;
        *(float4*)&g_tX[(size_t)idx * RR] = t;
        if (write_next) {
            g_XhatP[idx]        = v0 + v1 + v2 + v3;
            g_XhatP[NH + idx]   = v0 - v2;
            g_XhatP[2*NH + idx] = v0 - v1 + v2 - v3;
        }
    }
}

// Head: 8 targets per block, lin1_w cached in smem.
__global__ void k_head(const int* __restrict__ target_x, const int* __restrict__ target,
                       const float* __restrict__ l1w, const float* __restrict__ l1b,
                       const float* __restrict__ l2w, const float* __restrict__ l2b,
                       float* __restrict__ y_out) {
    extern __shared__ float dsm[];
    float* sw1 = dsm;                // 256*64
    float* sf  = sw1 + 256 * HH;     // 256
    float* sp  = sf + 256;           // 4*64
    float* szz = sp + 256;           // 64
    float* sy  = szz + 64;           // 16
    int tid = threadIdx.x;
    for (int q = tid; q < 256 * HH; q += 256) sw1[q] = l1w[q];
    int h = tid & 63, part = tid >> 6;
    for (int tt = 0; tt < 8; tt++) {
        int t = blockIdx.x * 8 + tt;
        __syncthreads();
        int n = target_x[t];
        sf[tid] = g_tX[(size_t)n * 256 + tid];
        __syncthreads();
        float acc = 0.f;
        #pragma unroll 8
        for (int q = part * 64; q < part * 64 + 64; q++)
            acc += sf[q] * sw1[q * 64 + h];
        sp[part * 64 + h] = acc;
        __syncthreads();
        if (tid < HH) {
            float z = sp[tid] + sp[64 + tid] + sp[128 + tid] + sp[192 + tid] + l1b[tid];
            szz[tid] = z > 0.f ? z : 0.f;
        }
        __syncthreads();
        if (tid < CC) {
            float yv = l2b[tid];
            #pragma unroll 8
            for (int hh = 0; hh < HH; hh++) yv += szz[hh] * l2w[hh * CC + tid];
            sy[tid] = yv;
            y_out[t * CC + tid] = yv;
        }
        __syncthreads();
        if (tid == 0) {
            float mx = sy[0];
            for (int c = 1; c < CC; c++) mx = fmaxf(mx, sy[c]);
            float se = 0.f;
            for (int c = 0; c < CC; c++) se += expf(sy[c] - mx);
            g_losses[t] = mx + logf(se) - sy[target[t]];
        }
    }
}

__global__ void k_loss_reduce(float* __restrict__ loss_ptr) {
    __shared__ float s[256];
    int tid = threadIdx.x;
    s[tid] = g_losses[tid] + g_losses[tid + 256];
    __syncthreads();
    for (int o = 128; o > 0; o >>= 1) {
        if (tid < o) s[tid] += s[tid + o];
        __syncthreads();
    }
    if (tid == 0) *loss_ptr = s[0] / (float)TT;
}

extern "C" void kernel_launch(void* const* d_in, const int* in_sizes, int n_in,
                              void* d_out, int out_size) {
    const float* A        = (const float*)d_in[0];
    const float* X        = (const float*)d_in[1];
    const int*   target_x = (const int*)  d_in[2];
    const int*   target   = (const int*)  d_in[3];
    const float* gw1      = (const float*)d_in[4];
    const float* gb1      = (const float*)d_in[5];
    const float* gw2      = (const float*)d_in[6];
    const float* gb2      = (const float*)d_in[7];
    const float* mw       = (const float*)d_in[8];
    const float* l1w      = (const float*)d_in[9];
    const float* l1b      = (const float*)d_in[10];
    const float* l2w      = (const float*)d_in[11];
    const float* l2b      = (const float*)d_in[12];

    float* outf = (float*)d_out;
    float* loss_ptr = nullptr;
    float* y_dst;
    if (out_size >= TT * CC + 1)  { loss_ptr = outf; y_dst = outf + 1; }
    else if (out_size >= TT * CC) { y_dst = outf; }
    else {
        loss_ptr = outf;
        void* p = nullptr; cudaGetSymbolAddress(&p, g_yscratch);
        y_dst = (float*)p;
    }

    // opt-in smem (host-side; happens once at capture, free at replay)
    const int XW1_SMEM  = (FINN * HH + 64 * FINN) * 4;              // 64 KB
    const int DHAT_SMEM = (3 * HH * HH) * 4 + 32 * HH * 16;         // 80 KB
    const int HEAD_SMEM = (256 * HH + 256 + 256 + 64 + 16) * 4;     // ~66 KB
    cudaFuncSetAttribute(k_xw1,  cudaFuncAttributeMaxDynamicSharedMemorySize, XW1_SMEM);
    cudaFuncSetAttribute(k_dhat, cudaFuncAttributeMaxDynamicSharedMemorySize, DHAT_SMEM);
    cudaFuncSetAttribute(k_head, cudaFuncAttributeMaxDynamicSharedMemorySize, HEAD_SMEM);

    // 1) sparsity pattern + degrees (single DRAM pass over A)
    k_build<<<RR * NN / 8, 256>>>(A);
    k_fill_dw<<<RR * NN / 8, 256>>>();
    k_what_all<<<(LLAY * HH * HH + 255) / 256, 256>>>(mw);

    // 2) per-relation GCN x2 (sparse, d folded into Y)
    k_xw1<<<dim3(NN / 64, RR), 256, XW1_SMEM>>>(X, gw1);
    k_spmm_gcn<<<RR * NN / 4, 256>>>(gb1);
    k_hw2<<<dim3(NN / 64, RR), 256>>>(gw2);
    k_spmm_gcn<<<RR * NN / 4, 256>>>(gb2);

    // 3) MRGCO layers
    k_xhat<<<(NH + 255) / 256, 256>>>();
    for (int l = 0; l < LLAY; l++) {
        k_spmm3<<<NN, 192>>>();
        k_dhat<<<NN / 32, 256, DHAT_SMEM>>>(l, l + 1 < LLAY);
    }

    // 4) head + deterministic loss reduction
    k_head<<<TT / 8, 256, HEAD_SMEM>>>(target_x, target, l1w, l1b, l2w, l2b, y_dst);
    if (loss_ptr) k_loss_reduce<<<1, 256>>>(loss_ptr);
}

// round 3
// speedup vs baseline: 1.0625x; 1.0625x over previous
#include <cuda_runtime.h>
#include <math.h>

#define NN    4096
#define RR    4
#define FINN  128
#define HH    64
#define CC    16
#define LLAY  2
#define TT    512
#define ELL_S 128   // max nnz/row (mean ~21.5, sigma ~4.5 -> huge margin)
#define NH    (NN*HH)

// ---- static scratch ----
__device__ float g_d   [RR*NN];                       // D^-1/2 per (relation,row)
__device__ int   g_cnt [RR*NN];
__device__ int   g_cols[RR*NN*ELL_S];                 // ELL column indices
__device__ float g_dw  [RR*NN*ELL_S];                 // d_j per slot
__device__ __align__(16) float g_Y [RR*NN*HH];        // dense GEMM out, pre-scaled by d_j
__device__ __align__(16) float g_h [RR*NN*HH];        // GCN hidden, planes [r][j][h]
__device__ __align__(16) float g_tX[NN*HH*RR];        // interleaved [i][h][r] (head input)
__device__ __align__(16) float g_X02[NN*2*HH];        // packed planes {0,2} per node
__device__ float g_X1  [NN*HH];                       // plane 1
__device__ float4 g_O4 [NN*HH];                       // Ohat interleaved {k0,k1,k2,pad}
__device__ float g_What[LLAY*3*HH*HH];
__device__ float g_losses[TT];
__device__ float g_yscratch[TT*CC];

// ------------------------------------------------------------------
// K1: single dense pass over A -> ELL pattern + degrees. Warp per row.
// ------------------------------------------------------------------
__global__ void k_build(const float* __restrict__ A) {
    int warp = (blockIdx.x * blockDim.x + threadIdx.x) >> 5;
    int lane = threadIdx.x & 31;
    if (warp >= RR * NN) return;
    int i = warp & (NN - 1);
    const float4* row4 = (const float4*)(A + (size_t)warp * NN);
    int* crow = g_cols + (size_t)warp * ELL_S;
    unsigned bm = (1u << lane) - 1u;
    int cnt = 0;
    #pragma unroll 4
    for (int it = 0; it < NN / 128; it++) {
        float4 v = __ldcs(&row4[it * 32 + lane]);
        int jb = it * 128 + lane * 4;
        bool n0 = (v.x != 0.f) || (jb     == i);
        bool n1 = (v.y != 0.f) || (jb + 1 == i);
        bool n2 = (v.z != 0.f) || (jb + 2 == i);
        bool n3 = (v.w != 0.f) || (jb + 3 == i);
        unsigned m0 = __ballot_sync(0xffffffffu, n0);
        unsigned m1 = __ballot_sync(0xffffffffu, n1);
        unsigned m2 = __ballot_sync(0xffffffffu, n2);
        unsigned m3 = __ballot_sync(0xffffffffu, n3);
        int p = cnt + __popc(m0 & bm) + __popc(m1 & bm) + __popc(m2 & bm) + __popc(m3 & bm);
        if (n0) { if (p < ELL_S) crow[p] = jb;     p++; }
        if (n1) { if (p < ELL_S) crow[p] = jb + 1; p++; }
        if (n2) { if (p < ELL_S) crow[p] = jb + 2; p++; }
        if (n3) { if (p < ELL_S) crow[p] = jb + 3; p++; }
        cnt += __popc(m0) + __popc(m1) + __popc(m2) + __popc(m3);
    }
    if (cnt > ELL_S) cnt = ELL_S;
    if (lane == 0) {
        g_cnt[warp] = cnt;
        g_d[warp] = rsqrtf((float)cnt);   // rowsum == cnt (entries exactly 1.0), cnt>=1
    }
}

// K1b: dw[row][s] = d[r, col]
__global__ void k_fill_dw() {
    int row = (blockIdx.x * blockDim.x + threadIdx.x) >> 5;
    int lane = threadIdx.x & 31;
    if (row >= RR * NN) return;
    int rbase = row & ~(NN - 1);
    int cnt = g_cnt[row];
    const int* crow = g_cols + (size_t)row * ELL_S;
    float* dwr = g_dw + (size_t)row * ELL_S;
    for (int s = lane; s < cnt; s += 32) dwr[s] = g_d[rbase + crow[s]];
}

// Both layers' frequency-domain weights (cosine transform over r).
__global__ void k_what_all(const float* __restrict__ W) {
    int idx = blockIdx.x * blockDim.x + threadIdx.x;
    if (idx >= LLAY * HH * HH) return;
    int l = idx / (HH * HH), q = idx % (HH * HH);
    const float* p = W + (size_t)idx * RR;
    float w0 = p[0], w1 = p[1], w2 = p[2], w3 = p[3];
    float* base = g_What + (size_t)l * 3 * HH * HH;
    base[q]           = w0 + w1 + w2 + w3;
    base[HH*HH + q]   = w0 - w2;
    base[2*HH*HH + q] = w0 - w1 + w2 - w3;
}

// K2: Y[r,j,:] = d_rj * (X[j,:] @ W1[r]).  W in smem (32KB), X warp-uniform global.
__global__ void k_xw1(const float* __restrict__ X, const float* __restrict__ W1) {
    __shared__ float sW[FINN * HH];
    int r = blockIdx.y, i0 = blockIdx.x * 64, tid = threadIdx.x;
    const float* wg = W1 + (size_t)r * FINN * HH;
    for (int q = tid; q < FINN * HH; q += 256) sW[q] = wg[q];
    __syncthreads();
    int h = tid & 63, rg = tid >> 6;
    int base = i0 + rg * 16;
    float acc[16];
    #pragma unroll
    for (int rr = 0; rr < 16; rr++) acc[rr] = 0.f;
    for (int f = 0; f < FINN; f += 4) {
        float w0 = sW[f*64+h], w1 = sW[(f+1)*64+h], w2 = sW[(f+2)*64+h], w3 = sW[(f+3)*64+h];
        #pragma unroll
        for (int rr = 0; rr < 16; rr++) {
            float4 x = __ldg((const float4*)&X[(size_t)(base + rr) * FINN + f]);
            acc[rr] += x.x*w0 + x.y*w1 + x.z*w2 + x.w*w3;
        }
    }
    #pragma unroll
    for (int rr = 0; rr < 16; rr++) {
        int gi = (r << 12) + base + rr;
        g_Y[(size_t)gi * HH + h] = g_d[gi] * acc[rr];
    }
}

// K4a: Y[r,j,:] = d_rj * (h[r,j,:] @ W2[r]).  W in smem (16KB), h warp-uniform global.
__global__ void k_hw2(const float* __restrict__ W2) {
    __shared__ float sW[HH * HH];
    int r = blockIdx.y, i0 = blockIdx.x * 64, tid = threadIdx.x;
    const float* wg = W2 + (size_t)r * HH * HH;
    for (int q = tid; q < HH * HH; q += 256) sW[q] = wg[q];
    __syncthreads();
    int h = tid & 63, rg = tid >> 6;
    int base = i0 + rg * 16;
    const float* hb = g_h + ((size_t)r << 12) * HH;
    float acc[16];
    #pragma unroll
    for (int rr = 0; rr < 16; rr++) acc[rr] = 0.f;
    for (int f = 0; f < HH; f += 4) {
        float w0 = sW[f*64+h], w1 = sW[(f+1)*64+h], w2 = sW[(f+2)*64+h], w3 = sW[(f+3)*64+h];
        #pragma unroll
        for (int rr = 0; rr < 16; rr++) {
            float4 x = *(const float4*)&hb[(size_t)(base + rr) * HH + f];
            acc[rr] += x.x*w0 + x.y*w1 + x.z*w2 + x.w*w3;
        }
    }
    #pragma unroll
    for (int rr = 0; rr < 16; rr++) {
        int gi = (r << 12) + base + rr;
        g_Y[(size_t)gi * HH + h] = g_d[gi] * acc[rr];
    }
}

// K3: first GCN aggregation -> plane layout g_h.
__global__ void k_spmm_gcn(const float* __restrict__ bias) {
    int row = blockIdx.x * 4 + (threadIdx.x >> 6);
    int h = threadIdx.x & 63;
    int r = row >> 12;
    int cnt = g_cnt[row];
    const int* crow = g_cols + (size_t)row * ELL_S;
    const float* Yb = g_Y + ((size_t)r << 12) * HH;
    float acc = 0.f;
    int s = 0;
    for (; s + 4 <= cnt; s += 4) {
        int j0 = crow[s], j1 = crow[s+1], j2 = crow[s+2], j3 = crow[s+3];
        acc += Yb[(size_t)j0*HH+h] + Yb[(size_t)j1*HH+h]
             + Yb[(size_t)j2*HH+h] + Yb[(size_t)j3*HH+h];
    }
    for (; s < cnt; s++) acc += Yb[(size_t)crow[s]*HH+h];
    float v = g_d[row] * acc + bias[r * HH + h];
    g_h[(size_t)row * HH + h] = v > 0.f ? v : 0.f;
}

// K4b: second GCN aggregation, all 4 relations of node i in one block,
// fused frequency-plane packing epilogue (replaces k_xhat).
__global__ void k_spmm_xhat(const float* __restrict__ bias) {
    int i = blockIdx.x, tid = threadIdx.x;
    int r = tid >> 6, h = tid & 63;
    int row = (r << 12) + i;
    int cnt = g_cnt[row];
    const int* crow = g_cols + (size_t)row * ELL_S;
    const float* Yb = g_Y + ((size_t)r << 12) * HH;
    float acc = 0.f;
    int s = 0;
    for (; s + 4 <= cnt; s += 4) {
        int j0 = crow[s], j1 = crow[s+1], j2 = crow[s+2], j3 = crow[s+3];
        acc += Yb[(size_t)j0*HH+h] + Yb[(size_t)j1*HH+h]
             + Yb[(size_t)j2*HH+h] + Yb[(size_t)j3*HH+h];
    }
    for (; s < cnt; s++) acc += Yb[(size_t)crow[s]*HH+h];
    float v = g_d[row] * acc + bias[r * HH + h];
    v = v > 0.f ? v : 0.f;
    __shared__ float sh[4][HH];
    sh[r][h] = v;
    __syncthreads();
    if (tid < HH) {
        float x0 = sh[0][tid], x1 = sh[1][tid], x2 = sh[2][tid], x3 = sh[3][tid];
        g_X02[(size_t)i * 128 + tid]      = x0 + x1 + x2 + x3;   // plane 0
        g_X02[(size_t)i * 128 + 64 + tid] = x0 - x1 + x2 - x3;   // plane 2
        g_X1 [(size_t)i * 64 + tid]       = x0 - x2;             // plane 1
    }
}

// Chat_k via packed-plane gathers; fused Ohat epilogue (ifft.real then fft.real).
// threads 0-127: planes {0,2} packed, all 4 relations. threads 128-191: plane 1, rel {0,2}.
__global__ void k_spmm3() {
    int i = blockIdx.x, tid = threadIdx.x;   // 192 threads
    __shared__ float sc[3][HH];
    if (tid < 128) {
        int hh = tid;
        float acc = 0.f;
        #pragma unroll
        for (int r = 0; r < RR; r++) {
            int row = (r << 12) + i;
            int cnt = g_cnt[row];
            const int*   crow = g_cols + (size_t)row * ELL_S;
            const float* dwr  = g_dw   + (size_t)row * ELL_S;
            float s = 0.f;
            int ss = 0;
            for (; ss + 4 <= cnt; ss += 4) {
                int j0 = crow[ss], j1 = crow[ss+1], j2 = crow[ss+2], j3 = crow[ss+3];
                float w0 = dwr[ss], w1 = dwr[ss+1], w2 = dwr[ss+2], w3 = dwr[ss+3];
                s += w0 * g_X02[(size_t)j0*128+hh] + w1 * g_X02[(size_t)j1*128+hh]
                   + w2 * g_X02[(size_t)j2*128+hh] + w3 * g_X02[(size_t)j3*128+hh];
            }
            for (; ss < cnt; ss++) s += dwr[ss] * g_X02[(size_t)crow[ss]*128+hh];
            float coef = (hh < 64) ? 1.f : ((r & 1) ? -1.f : 1.f);  // Mc[0][r] / Mc[2][r]
            acc += coef * g_d[row] * s;
        }
        if (hh < 64) sc[0][hh] = acc; else sc[2][hh - 64] = acc;
    } else {
        int h = tid - 128;
        float acc = 0.f;
        #pragma unroll
        for (int rr = 0; rr < 2; rr++) {
            int r = rr * 2;                       // relations 0, 2 (Mc[1][r] = +1, -1)
            int row = (r << 12) + i;
            int cnt = g_cnt[row];
            const int*   crow = g_cols + (size_t)row * ELL_S;
            const float* dwr  = g_dw   + (size_t)row * ELL_S;
            float s = 0.f;
            int ss = 0;
            for (; ss + 4 <= cnt; ss += 4) {
                int j0 = crow[ss], j1 = crow[ss+1], j2 = crow[ss+2], j3 = crow[ss+3];
                float w0 = dwr[ss], w1 = dwr[ss+1], w2 = dwr[ss+2], w3 = dwr[ss+3];
                s += w0 * g_X1[(size_t)j0*64+h] + w1 * g_X1[(size_t)j1*64+h]
                   + w2 * g_X1[(size_t)j2*64+h] + w3 * g_X1[(size_t)j3*64+h];
            }
            for (; ss < cnt; ss++) s += dwr[ss] * g_X1[(size_t)crow[ss]*64+h];
            acc += (rr == 0 ? 1.f : -1.f) * g_d[row] * s;
        }
        sc[1][h] = acc;
    }
    __syncthreads();
    if (tid < HH) {
        float C0 = sc[0][tid], C1 = sc[1][tid], C2 = sc[2][tid];
        float O0 = 0.25f * (C0 + 2.f*C1 + C2);
        float O1 = 0.25f * (C0 - C2);
        float O2 = 0.25f * (C0 - 2.f*C1 + C2);
        float O3 = O1;
        float4 o;
        o.x = O0 + O1 + O2 + O3;
        o.y = O0 - O2;
        o.z = O0 - O1 + O2 - O3;
        o.w = 0.f;
        g_O4[(size_t)i * HH + tid] = o;
    }
}

// Dhat_k = Ohat_k @ What_k ; fused epilogue: ifft.real + relu -> tX (interleaved)
// and packed planes for the next layer.
__global__ void k_dhat(int layer, int write_next) {
    extern __shared__ float dsm[];
    float*  sW = dsm;                          // 3*HH*HH floats (48KB)
    float4* sO = (float4*)(dsm + 3 * HH * HH); // 32*HH float4 (32KB)
    int i0 = blockIdx.x * 32, tid = threadIdx.x;
    const float* wb = g_What + (size_t)layer * 3 * HH * HH;
    for (int q = tid; q < 3 * HH * HH; q += 256) sW[q] = wb[q];
    for (int q = tid; q < 32 * HH; q += 256)
        sO[q] = g_O4[(size_t)(i0 + (q >> 6)) * HH + (q & 63)];
    __syncthreads();
    int l = tid & 63, rg = tid >> 6;
    float a0[8], a1[8], a2[8];
    #pragma unroll
    for (int rr = 0; rr < 8; rr++) { a0[rr] = 0.f; a1[rr] = 0.f; a2[rr] = 0.f; }
    #pragma unroll 4
    for (int j = 0; j < HH; j++) {
        float w0 = sW[j*64+l], w1 = sW[HH*HH + j*64+l], w2 = sW[2*HH*HH + j*64+l];
        #pragma unroll
        for (int rr = 0; rr < 8; rr++) {
            float4 o = sO[(rg * 8 + rr) * HH + j];
            a0[rr] += o.x * w0; a1[rr] += o.y * w1; a2[rr] += o.z * w2;
        }
    }
    #pragma unroll
    for (int rr = 0; rr < 8; rr++) {
        float D0 = a0[rr], D1 = a1[rr], D2 = a2[rr];
        float v0 = 0.25f * (D0 + 2.f*D1 + D2);
        float v1 = 0.25f * (D0 - D2);
        float v2 = 0.25f * (D0 - 2.f*D1 + D2);
        float v3 = v1;
        v0 = v0 > 0.f ? v0 : 0.f;  v1 = v1 > 0.f ? v1 : 0.f;
        v2 = v2 > 0.f ? v2 : 0.f;  v3 = v3 > 0.f ? v3 : 0.f;
        int node = i0 + rg * 8 + rr;
        float4 t; t.x = v0; t.y = v1; t.z = v2; t.w = v3;
        *(float4*)&g_tX[((size_t)node * HH + l) * RR] = t;
        if (write_next) {
            g_X02[(size_t)node * 128 + l]      = v0 + v1 + v2 + v3;
            g_X02[(size_t)node * 128 + 64 + l] = v0 - v1 + v2 - v3;
            g_X1 [(size_t)node * 64 + l]       = v0 - v2;
        }
    }
}

// Head: 8 targets per block, lin1_w cached in smem.
__global__ void k_head(const int* __restrict__ target_x, const int* __restrict__ target,
                       const float* __restrict__ l1w, const float* __restrict__ l1b,
                       const float* __restrict__ l2w, const float* __restrict__ l2b,
                       float* __restrict__ y_out) {
    extern __shared__ float dsm[];
    float* sw1 = dsm;                // 256*64
    float* sf  = sw1 + 256 * HH;     // 256
    float* sp  = sf + 256;           // 4*64
    float* szz = sp + 256;           // 64
    float* sy  = szz + 64;           // 16
    int tid = threadIdx.x;
    for (int q = tid; q < 256 * HH; q += 256) sw1[q] = l1w[q];
    int h = tid & 63, part = tid >> 6;
    for (int tt = 0; tt < 8; tt++) {
        int t = blockIdx.x * 8 + tt;
        __syncthreads();
        int n = target_x[t];
        sf[tid] = g_tX[(size_t)n * 256 + tid];
        __syncthreads();
        float acc = 0.f;
        #pragma unroll 8
        for (int q = part * 64; q < part * 64 + 64; q++)
            acc += sf[q] * sw1[q * 64 + h];
        sp[part * 64 + h] = acc;
        __syncthreads();
        if (tid < HH) {
            float z = sp[tid] + sp[64 + tid] + sp[128 + tid] + sp[192 + tid] + l1b[tid];
            szz[tid] = z > 0.f ? z : 0.f;
        }
        __syncthreads();
        if (tid < CC) {
            float yv = l2b[tid];
            #pragma unroll 8
            for (int hh = 0; hh < HH; hh++) yv += szz[hh] * l2w[hh * CC + tid];
            sy[tid] = yv;
            y_out[t * CC + tid] = yv;
        }
        __syncthreads();
        if (tid == 0) {
            float mx = sy[0];
            for (int c = 1; c < CC; c++) mx = fmaxf(mx, sy[c]);
            float se = 0.f;
            for (int c = 0; c < CC; c++) se += expf(sy[c] - mx);
            g_losses[t] = mx + logf(se) - sy[target[t]];
        }
    }
}

__global__ void k_loss_reduce(float* __restrict__ loss_ptr) {
    __shared__ float s[256];
    int tid = threadIdx.x;
    s[tid] = g_losses[tid] + g_losses[tid + 256];
    __syncthreads();
    for (int o = 128; o > 0; o >>= 1) {
        if (tid < o) s[tid] += s[tid + o];
        __syncthreads();
    }
    if (tid == 0) *loss_ptr = s[0] / (float)TT;
}

extern "C" void kernel_launch(void* const* d_in, const int* in_sizes, int n_in,
                              void* d_out, int out_size) {
    const float* A        = (const float*)d_in[0];
    const float* X        = (const float*)d_in[1];
    const int*   target_x = (const int*)  d_in[2];
    const int*   target   = (const int*)  d_in[3];
    const float* gw1      = (const float*)d_in[4];
    const float* gb1      = (const float*)d_in[5];
    const float* gw2      = (const float*)d_in[6];
    const float* gb2      = (const float*)d_in[7];
    const float* mw       = (const float*)d_in[8];
    const float* l1w      = (const float*)d_in[9];
    const float* l1b      = (const float*)d_in[10];
    const float* l2w      = (const float*)d_in[11];
    const float* l2b      = (const float*)d_in[12];

    float* outf = (float*)d_out;
    float* loss_ptr = nullptr;
    float* y_dst;
    if (out_size >= TT * CC + 1)  { loss_ptr = outf; y_dst = outf + 1; }
    else if (out_size >= TT * CC) { y_dst = outf; }
    else {
        loss_ptr = outf;
        void* p = nullptr; cudaGetSymbolAddress(&p, g_yscratch);
        y_dst = (float*)p;
    }

    const int DHAT_SMEM = (3 * HH * HH) * 4 + 32 * HH * 16;         // 80 KB
    const int HEAD_SMEM = (256 * HH + 256 + 256 + 64 + 16) * 4;     // ~66 KB
    cudaFuncSetAttribute(k_dhat, cudaFuncAttributeMaxDynamicSharedMemorySize, DHAT_SMEM);
    cudaFuncSetAttribute(k_head, cudaFuncAttributeMaxDynamicSharedMemorySize, HEAD_SMEM);

    // 1) sparsity pattern + degrees (single DRAM pass over A)
    k_build<<<RR * NN / 8, 256>>>(A);
    k_fill_dw<<<RR * NN / 8, 256>>>();
    k_what_all<<<(LLAY * HH * HH + 255) / 256, 256>>>(mw);

    // 2) per-relation GCN x2
    k_xw1<<<dim3(NN / 64, RR), 256>>>(X, gw1);
    k_spmm_gcn<<<RR * NN / 4, 256>>>(gb1);
    k_hw2<<<dim3(NN / 64, RR), 256>>>(gw2);
    k_spmm_xhat<<<NN, 256>>>(gb2);   // fused plane packing

    // 3) MRGCO layers
    for (int l = 0; l < LLAY; l++) {
        k_spmm3<<<NN, 192>>>();
        k_dhat<<<NN / 32, 256, DHAT_SMEM>>>(l, l + 1 < LLAY);
    }

    // 4) head + deterministic loss reduction
    k_head<<<TT / 8, 256, HEAD_SMEM>>>(target_x, target, l1w, l1b, l2w, l2b, y_dst);
    if (loss_ptr) k_loss_reduce<<<1, 256>>>(loss_ptr);
}

// round 4
// speedup vs baseline: 1.2036x; 1.1329x over previous
#include <cuda_runtime.h>
#include <math.h>

#define NN    4096
#define RR    4
#define FINN  128
#define HH    64
#define CC    16
#define LLAY  2
#define TT    512
#define ELL_S 128   // max nnz/row (mean ~21.5, sigma ~4.5 -> huge margin)
#define NH    (NN*HH)

// ---- static scratch ----
__device__ float g_d   [RR*NN];                       // D^-1/2 per (relation,row)
__device__ int   g_cnt [RR*NN];
__device__ int   g_cols[RR*NN*ELL_S];                 // ELL column indices
__device__ float g_dw  [RR*NN*ELL_S];                 // d_j per slot
__device__ __align__(16) float g_Y [RR*NN*HH];        // dense GEMM out, pre-scaled by d_j
__device__ __align__(16) float g_h [RR*NN*HH];        // GCN hidden, planes [r][j][h]
__device__ __align__(16) float g_tX[NN*HH*RR];        // interleaved [i][h][r] (head input)
__device__ __align__(16) float g_X02[NN*2*HH];        // packed planes {0,2} per node
__device__ __align__(16) float g_X1 [NN*HH];          // plane 1
__device__ float4 g_O4 [NN*HH];                       // Ohat interleaved {k0,k1,k2,pad}
__device__ float g_What[LLAY*3*HH*HH];
__device__ float g_losses[TT];
__device__ float g_yscratch[TT*CC];

// ------------------------------------------------------------------
// K1: single dense pass over A -> ELL pattern + degrees. Warp per row.
// ------------------------------------------------------------------
__global__ void k_build(const float* __restrict__ A) {
    int warp = (blockIdx.x * blockDim.x + threadIdx.x) >> 5;
    int lane = threadIdx.x & 31;
    if (warp >= RR * NN) return;
    int i = warp & (NN - 1);
    const float4* row4 = (const float4*)(A + (size_t)warp * NN);
    int* crow = g_cols + (size_t)warp * ELL_S;
    unsigned bm = (1u << lane) - 1u;
    int cnt = 0;
    #pragma unroll 4
    for (int it = 0; it < NN / 128; it++) {
        float4 v = __ldcs(&row4[it * 32 + lane]);
        int jb = it * 128 + lane * 4;
        bool n0 = (v.x != 0.f) || (jb     == i);
        bool n1 = (v.y != 0.f) || (jb + 1 == i);
        bool n2 = (v.z != 0.f) || (jb + 2 == i);
        bool n3 = (v.w != 0.f) || (jb + 3 == i);
        unsigned m0 = __ballot_sync(0xffffffffu, n0);
        unsigned m1 = __ballot_sync(0xffffffffu, n1);
        unsigned m2 = __ballot_sync(0xffffffffu, n2);
        unsigned m3 = __ballot_sync(0xffffffffu, n3);
        int p = cnt + __popc(m0 & bm) + __popc(m1 & bm) + __popc(m2 & bm) + __popc(m3 & bm);
        if (n0) { if (p < ELL_S) crow[p] = jb;     p++; }
        if (n1) { if (p < ELL_S) crow[p] = jb + 1; p++; }
        if (n2) { if (p < ELL_S) crow[p] = jb + 2; p++; }
        if (n3) { if (p < ELL_S) crow[p] = jb + 3; p++; }
        cnt += __popc(m0) + __popc(m1) + __popc(m2) + __popc(m3);
    }
    if (cnt > ELL_S) cnt = ELL_S;
    if (lane == 0) {
        g_cnt[warp] = cnt;
        g_d[warp] = rsqrtf((float)cnt);   // rowsum == cnt (entries exactly 1.0), cnt>=1
    }
}

// K1b: fused prep — blocks [0,2048): dw[row][s] = d[r,col]; blocks [2048,2080): What.
__global__ void k_prep(const float* __restrict__ W) {
    int b = blockIdx.x;
    if (b < 2048) {
        int row = b * 8 + (threadIdx.x >> 5);
        int lane = threadIdx.x & 31;
        int rbase = row & ~(NN - 1);
        int cnt = g_cnt[row];
        const int* crow = g_cols + (size_t)row * ELL_S;
        float* dwr = g_dw + (size_t)row * ELL_S;
        for (int s = lane; s < cnt; s += 32) dwr[s] = g_d[rbase + crow[s]];
    } else {
        int idx = (b - 2048) * 256 + threadIdx.x;   // < LLAY*HH*HH = 8192
        const float* p = W + (size_t)idx * RR;
        float w0 = p[0], w1 = p[1], w2 = p[2], w3 = p[3];
        int l = idx >> 12, q = idx & 4095;
        float* base = g_What + (size_t)l * 3 * HH * HH;
        base[q]           = w0 + w1 + w2 + w3;
        base[HH*HH + q]   = w0 - w2;
        base[2*HH*HH + q] = w0 - w1 + w2 - w3;
    }
}

// K2: Y[r,j,:] = d_rj * (X[j,:] @ W1[r]).  32 rows/block, grid 512.
__global__ void __launch_bounds__(256) k_xw1(const float* __restrict__ X,
                                             const float* __restrict__ W1) {
    extern __shared__ float dsm[];
    float* sW = dsm;                 // FINN*HH = 32KB
    float* sX = dsm + FINN * HH;     // 32*FINN = 16KB
    int r = blockIdx.y, i0 = blockIdx.x * 32, tid = threadIdx.x;
    const float4* wg4 = (const float4*)(W1 + (size_t)r * FINN * HH);
    float4* sW4 = (float4*)sW;
    for (int q = tid; q < FINN * HH / 4; q += 256) sW4[q] = wg4[q];
    const float4* xg4 = (const float4*)(X + (size_t)i0 * FINN);
    float4* sX4 = (float4*)sX;
    for (int q = tid; q < 32 * FINN / 4; q += 256) sX4[q] = xg4[q];
    __syncthreads();
    int h = tid & 63, rg = tid >> 6;
    const float* sXb = sX + rg * 8 * FINN;
    float acc[8];
    #pragma unroll
    for (int rr = 0; rr < 8; rr++) acc[rr] = 0.f;
    for (int f = 0; f < FINN; f += 4) {
        float w0 = sW[f*64+h], w1 = sW[(f+1)*64+h], w2 = sW[(f+2)*64+h], w3 = sW[(f+3)*64+h];
        #pragma unroll
        for (int rr = 0; rr < 8; rr++) {
            float4 x = *(const float4*)&sXb[rr * FINN + f];
            acc[rr] += x.x*w0 + x.y*w1 + x.z*w2 + x.w*w3;
        }
    }
    #pragma unroll
    for (int rr = 0; rr < 8; rr++) {
        int gi = (r << 12) + i0 + rg * 8 + rr;
        g_Y[(size_t)gi * HH + h] = g_d[gi] * acc[rr];
    }
}

// K4a: Y[r,j,:] = d_rj * (h[r,j,:] @ W2[r]).  32 rows/block, grid 512.
__global__ void __launch_bounds__(256) k_hw2(const float* __restrict__ W2) {
    __shared__ float sW[HH * HH];    // 16KB
    __shared__ float sX[32 * HH];    // 8KB
    int r = blockIdx.y, i0 = blockIdx.x * 32, tid = threadIdx.x;
    const float4* wg4 = (const float4*)(W2 + (size_t)r * HH * HH);
    float4* sW4 = (float4*)sW;
    for (int q = tid; q < HH * HH / 4; q += 256) sW4[q] = wg4[q];
    const float4* hg4 = (const float4*)(g_h + ((size_t)((r << 12) + i0)) * HH);
    float4* sX4 = (float4*)sX;
    for (int q = tid; q < 32 * HH / 4; q += 256) sX4[q] = hg4[q];
    __syncthreads();
    int h = tid & 63, rg = tid >> 6;
    const float* sXb = sX + rg * 8 * HH;
    float acc[8];
    #pragma unroll
    for (int rr = 0; rr < 8; rr++) acc[rr] = 0.f;
    for (int f = 0; f < HH; f += 4) {
        float w0 = sW[f*64+h], w1 = sW[(f+1)*64+h], w2 = sW[(f+2)*64+h], w3 = sW[(f+3)*64+h];
        #pragma unroll
        for (int rr = 0; rr < 8; rr++) {
            float4 x = *(const float4*)&sXb[rr * HH + f];
            acc[rr] += x.x*w0 + x.y*w1 + x.z*w2 + x.w*w3;
        }
    }
    #pragma unroll
    for (int rr = 0; rr < 8; rr++) {
        int gi = (r << 12) + i0 + rg * 8 + rr;
        g_Y[(size_t)gi * HH + h] = g_d[gi] * acc[rr];
    }
}

// K3: first GCN aggregation -> plane layout g_h. Unroll 8 for MLP.
__global__ void k_spmm_gcn(const float* __restrict__ bias) {
    int row = blockIdx.x * 4 + (threadIdx.x >> 6);
    int h = threadIdx.x & 63;
    int r = row >> 12;
    int cnt = g_cnt[row];
    const int* crow = g_cols + (size_t)row * ELL_S;
    const float* Yb = g_Y + ((size_t)r << 12) * HH;
    float acc = 0.f;
    int s = 0;
    for (; s + 8 <= cnt; s += 8) {
        int j[8];
        #pragma unroll
        for (int u = 0; u < 8; u++) j[u] = crow[s + u];
        #pragma unroll
        for (int u = 0; u < 8; u++) acc += Yb[(size_t)j[u] * HH + h];
    }
    for (; s < cnt; s++) acc += Yb[(size_t)crow[s] * HH + h];
    float v = g_d[row] * acc + bias[r * HH + h];
    g_h[(size_t)row * HH + h] = v > 0.f ? v : 0.f;
}

// K4b: second GCN aggregation for all 4 relations of node i, fused plane packing.
__global__ void k_spmm_xhat(const float* __restrict__ bias) {
    int i = blockIdx.x, tid = threadIdx.x;
    int r = tid >> 6, h = tid & 63;
    int row = (r << 12) + i;
    int cnt = g_cnt[row];
    const int* crow = g_cols + (size_t)row * ELL_S;
    const float* Yb = g_Y + ((size_t)r << 12) * HH;
    float acc = 0.f;
    int s = 0;
    for (; s + 8 <= cnt; s += 8) {
        int j[8];
        #pragma unroll
        for (int u = 0; u < 8; u++) j[u] = crow[s + u];
        #pragma unroll
        for (int u = 0; u < 8; u++) acc += Yb[(size_t)j[u] * HH + h];
    }
    for (; s < cnt; s++) acc += Yb[(size_t)crow[s] * HH + h];
    float v = g_d[row] * acc + bias[r * HH + h];
    v = v > 0.f ? v : 0.f;
    __shared__ float sh[4][HH];
    sh[r][h] = v;
    __syncthreads();
    if (tid < HH) {
        float x0 = sh[0][tid], x1 = sh[1][tid], x2 = sh[2][tid], x3 = sh[3][tid];
        g_X02[(size_t)i * 128 + tid]      = x0 + x1 + x2 + x3;   // plane 0
        g_X02[(size_t)i * 128 + 64 + tid] = x0 - x1 + x2 - x3;   // plane 2
        g_X1 [(size_t)i * 64 + tid]       = x0 - x2;             // plane 1
    }
}

// MRGCO gather: 640 threads; all 10 (relation, plane) gather-sums concurrent.
// threads [0,512): r=tid>>7, hh=tid&127 over packed planes {0,2}.
// threads [512,640): plane 1, relations {0,2}. Then smem reduce + Ohat epilogue.
__global__ void __launch_bounds__(640) k_spmm3() {
    int i = blockIdx.x, tid = threadIdx.x;
    __shared__ float part[4][128];
    __shared__ float part1[2][64];
    if (tid < 512) {
        int r = tid >> 7, hh = tid & 127;
        int row = (r << 12) + i;
        int cnt = g_cnt[row];
        const int*   crow = g_cols + (size_t)row * ELL_S;
        const float* dwr  = g_dw   + (size_t)row * ELL_S;
        float s = 0.f;
        int ss = 0;
        for (; ss + 8 <= cnt; ss += 8) {
            int j[8]; float w[8];
            #pragma unroll
            for (int u = 0; u < 8; u++) { j[u] = crow[ss+u]; w[u] = dwr[ss+u]; }
            #pragma unroll
            for (int u = 0; u < 8; u++) s += w[u] * g_X02[(size_t)j[u] * 128 + hh];
        }
        for (; ss < cnt; ss++) s += dwr[ss] * g_X02[(size_t)crow[ss] * 128 + hh];
        float coef = (hh < 64) ? 1.f : ((r & 1) ? -1.f : 1.f);   // Mc[0][r] / Mc[2][r]
        part[r][hh] = coef * g_d[row] * s;
    } else {
        int t2 = tid - 512;
        int rr = t2 >> 6, h = t2 & 63;
        int r = rr * 2;                                          // relations 0, 2
        int row = (r << 12) + i;
        int cnt = g_cnt[row];
        const int*   crow = g_cols + (size_t)row * ELL_S;
        const float* dwr  = g_dw   + (size_t)row * ELL_S;
        float s = 0.f;
        int ss = 0;
        for (; ss + 8 <= cnt; ss += 8) {
            int j[8]; float w[8];
            #pragma unroll
            for (int u = 0; u < 8; u++) { j[u] = crow[ss+u]; w[u] = dwr[ss+u]; }
            #pragma unroll
            for (int u = 0; u < 8; u++) s += w[u] * g_X1[(size_t)j[u] * 64 + h];
        }
        for (; ss < cnt; ss++) s += dwr[ss] * g_X1[(size_t)crow[ss] * 64 + h];
        part1[rr][h] = (rr ? -1.f : 1.f) * g_d[row] * s;         // Mc[1][0]=+1, Mc[1][2]=-1
    }
    __syncthreads();
    if (tid < HH) {
        float C0 = part[0][tid] + part[1][tid] + part[2][tid] + part[3][tid];
        float C2 = part[0][64+tid] + part[1][64+tid] + part[2][64+tid] + part[3][64+tid];
        float C1 = part1[0][tid] + part1[1][tid];
        float O0 = 0.25f * (C0 + 2.f*C1 + C2);
        float O1 = 0.25f * (C0 - C2);
        float O2 = 0.25f * (C0 - 2.f*C1 + C2);
        float O3 = O1;
        float4 o;
        o.x = O0 + O1 + O2 + O3;
        o.y = O0 - O2;
        o.z = O0 - O1 + O2 - O3;
        o.w = 0.f;
        g_O4[(size_t)i * HH + tid] = o;
    }
}

// Dhat_k = Ohat_k @ What_k ; 16 nodes/block (grid 256), W via L1.
// Fused epilogue: ifft.real + relu -> tX (interleaved) and next-layer planes.
__global__ void __launch_bounds__(256) k_dhat(int layer, int write_next) {
    __shared__ float4 sO[16 * HH];   // 16KB
    int i0 = blockIdx.x * 16, tid = threadIdx.x;
    for (int q = tid; q < 16 * HH; q += 256)
        sO[q] = g_O4[(size_t)(i0 + (q >> 6)) * HH + (q & 63)];
    __syncthreads();
    int l = tid & 63, ng = tid >> 6;
    const float* wb = g_What + (size_t)layer * 3 * HH * HH;
    float a0[4], a1[4], a2[4];
    #pragma unroll
    for (int rr = 0; rr < 4; rr++) { a0[rr] = 0.f; a1[rr] = 0.f; a2[rr] = 0.f; }
    #pragma unroll 4
    for (int j = 0; j < HH; j++) {
        float w0 = __ldg(&wb[j*64+l]);
        float w1 = __ldg(&wb[HH*HH + j*64+l]);
        float w2 = __ldg(&wb[2*HH*HH + j*64+l]);
        #pragma unroll
        for (int rr = 0; rr < 4; rr++) {
            float4 o = sO[(ng * 4 + rr) * HH + j];
            a0[rr] += o.x * w0; a1[rr] += o.y * w1; a2[rr] += o.z * w2;
        }
    }
    #pragma unroll
    for (int rr = 0; rr < 4; rr++) {
        float D0 = a0[rr], D1 = a1[rr], D2 = a2[rr];
        float v0 = 0.25f * (D0 + 2.f*D1 + D2);
        float v1 = 0.25f * (D0 - D2);
        float v2 = 0.25f * (D0 - 2.f*D1 + D2);
        float v3 = v1;
        v0 = v0 > 0.f ? v0 : 0.f;  v1 = v1 > 0.f ? v1 : 0.f;
        v2 = v2 > 0.f ? v2 : 0.f;  v3 = v3 > 0.f ? v3 : 0.f;
        int node = i0 + ng * 4 + rr;
        float4 t; t.x = v0; t.y = v1; t.z = v2; t.w = v3;
        *(float4*)&g_tX[((size_t)node * HH + l) * RR] = t;
        if (write_next) {
            g_X02[(size_t)node * 128 + l]      = v0 + v1 + v2 + v3;
            g_X02[(size_t)node * 128 + 64 + l] = v0 - v1 + v2 - v3;
            g_X1 [(size_t)node * 64 + l]       = v0 - v2;
        }
    }
}

// Head: 4 targets per block (grid 128), lin1_w cached in smem.
__global__ void k_head(const int* __restrict__ target_x, const int* __restrict__ target,
                       const float* __restrict__ l1w, const float* __restrict__ l1b,
                       const float* __restrict__ l2w, const float* __restrict__ l2b,
                       float* __restrict__ y_out) {
    extern __shared__ float dsm[];
    float* sw1 = dsm;                // 256*64 = 64KB
    float* sf  = sw1 + 256 * HH;     // 256
    float* sp  = sf + 256;           // 4*64
    float* szz = sp + 256;           // 64
    float* sy  = szz + 64;           // 16
    int tid = threadIdx.x;
    {
        const float4* w4 = (const float4*)l1w;
        float4* s4 = (float4*)sw1;
        for (int q = tid; q < 256 * HH / 4; q += 256) s4[q] = w4[q];
    }
    int h = tid & 63, part = tid >> 6;
    for (int tt = 0; tt < 4; tt++) {
        int t = blockIdx.x * 4 + tt;
        __syncthreads();
        int n = target_x[t];
        sf[tid] = g_tX[(size_t)n * 256 + tid];
        __syncthreads();
        float acc = 0.f;
        #pragma unroll 8
        for (int q = part * 64; q < part * 64 + 64; q++)
            acc += sf[q] * sw1[q * 64 + h];
        sp[part * 64 + h] = acc;
        __syncthreads();
        if (tid < HH) {
            float z = sp[tid] + sp[64 + tid] + sp[128 + tid] + sp[192 + tid] + l1b[tid];
            szz[tid] = z > 0.f ? z : 0.f;
        }
        __syncthreads();
        if (tid < CC) {
            float yv = l2b[tid];
            #pragma unroll 8
            for (int hh = 0; hh < HH; hh++) yv += szz[hh] * l2w[hh * CC + tid];
            sy[tid] = yv;
            y_out[t * CC + tid] = yv;
        }
        __syncthreads();
        if (tid == 0) {
            float mx = sy[0];
            for (int c = 1; c < CC; c++) mx = fmaxf(mx, sy[c]);
            float se = 0.f;
            for (int c = 0; c < CC; c++) se += expf(sy[c] - mx);
            g_losses[t] = mx + logf(se) - sy[target[t]];
        }
    }
}

__global__ void k_loss_reduce(float* __restrict__ loss_ptr) {
    __shared__ float s[256];
    int tid = threadIdx.x;
    s[tid] = g_losses[tid] + g_losses[tid + 256];
    __syncthreads();
    for (int o = 128; o > 0; o >>= 1) {
        if (tid < o) s[tid] += s[tid + o];
        __syncthreads();
    }
    if (tid == 0) *loss_ptr = s[0] / (float)TT;
}

extern "C" void kernel_launch(void* const* d_in, const int* in_sizes, int n_in,
                              void* d_out, int out_size) {
    const float* A        = (const float*)d_in[0];
    const float* X        = (const float*)d_in[1];
    const int*   target_x = (const int*)  d_in[2];
    const int*   target   = (const int*)  d_in[3];
    const float* gw1      = (const float*)d_in[4];
    const float* gb1      = (const float*)d_in[5];
    const float* gw2      = (const float*)d_in[6];
    const float* gb2      = (const float*)d_in[7];
    const float* mw       = (const float*)d_in[8];
    const float* l1w      = (const float*)d_in[9];
    const float* l1b      = (const float*)d_in[10];
    const float* l2w      = (const float*)d_in[11];
    const float* l2b      = (const float*)d_in[12];

    float* outf = (float*)d_out;
    float* loss_ptr = nullptr;
    float* y_dst;
    if (out_size >= TT * CC + 1)  { loss_ptr = outf; y_dst = outf + 1; }
    else if (out_size >= TT * CC) { y_dst = outf; }
    else {
        loss_ptr = outf;
        void* p = nullptr; cudaGetSymbolAddress(&p, g_yscratch);
        y_dst = (float*)p;
    }

    const int XW1_SMEM  = (FINN * HH + 32 * FINN) * 4;              // 48 KB
    const int HEAD_SMEM = (256 * HH + 256 + 256 + 64 + 16) * 4;     // ~66 KB
    cudaFuncSetAttribute(k_xw1,  cudaFuncAttributeMaxDynamicSharedMemorySize, XW1_SMEM);
    cudaFuncSetAttribute(k_head, cudaFuncAttributeMaxDynamicSharedMemorySize, HEAD_SMEM);

    // 1) sparsity pattern + degrees (single DRAM pass over A), then prep
    k_build<<<RR * NN / 8, 256>>>(A);
    k_prep<<<2048 + LLAY * HH * HH / 256, 256>>>(mw);

    // 2) per-relation GCN x2
    k_xw1<<<dim3(NN / 32, RR), 256, XW1_SMEM>>>(X, gw1);
    k_spmm_gcn<<<RR * NN / 4, 256>>>(gb1);
    k_hw2<<<dim3(NN / 32, RR), 256>>>(gw2);
    k_spmm_xhat<<<NN, 256>>>(gb2);   // fused plane packing

    // 3) MRGCO layers
    for (int l = 0; l < LLAY; l++) {
        k_spmm3<<<NN, 640>>>();
        k_dhat<<<NN / 16, 256>>>(l, l + 1 < LLAY);
    }

    // 4) head + deterministic loss reduction
    k_head<<<TT / 4, 256, HEAD_SMEM>>>(target_x, target, l1w, l1b, l2w, l2b, y_dst);
    if (loss_ptr) k_loss_reduce<<<1, 256>>>(loss_ptr);
}

// round 8
// speedup vs baseline: 1.2332x; 1.0245x over previous
#include <cuda_runtime.h>
#include <math.h>

#define NN    4096
#define RR    4
#define FINN  128
#define HH    64
#define CC    16
#define LLAY  2
#define TT    512
#define ELL_S 128   // max nnz/row (mean ~21.5, sigma ~4.5 -> huge margin)
#define NH    (NN*HH)

// ---- static scratch (fp32) ----
__device__ float g_d   [RR*NN];                       // D^-1/2 per (relation,row)
__device__ int   g_cnt [RR*NN];
__device__ int   g_cols[RR*NN*ELL_S];                 // ELL column indices
__device__ float g_dw  [RR*NN*ELL_S];                 // d_j per slot
__device__ __align__(16) float g_Y [RR*NN*HH];        // GEMM out, pre-scaled by d_j
__device__ __align__(16) float g_h [RR*NN*HH];        // GCN hidden, planes [r][j][h]
__device__ __align__(16) float g_tX[NN*HH*RR];        // interleaved [i][h][r] (head input)
// Ping-pong plane buffers: k_mrgco reads [src], writes [src^1] (cross-block
// read/write race otherwise — the R6/R7 failure).
__device__ __align__(16) float g_X02[2][NN*2*HH];     // packed planes {0,2} per node
__device__ __align__(16) float g_X1 [2][NN*HH];       // plane 1
__device__ float g_What[LLAY*3*HH*HH];
__device__ float g_losses[TT];
__device__ float g_yscratch[TT*CC];

// ------------------------------------------------------------------
// K1: single dense pass over A -> ELL pattern + degrees. Warp per row.
// ------------------------------------------------------------------
__global__ void k_build(const float* __restrict__ A) {
    int warp = (blockIdx.x * blockDim.x + threadIdx.x) >> 5;
    int lane = threadIdx.x & 31;
    if (warp >= RR * NN) return;
    int i = warp & (NN - 1);
    const float4* row4 = (const float4*)(A + (size_t)warp * NN);
    int* crow = g_cols + (size_t)warp * ELL_S;
    unsigned bm = (1u << lane) - 1u;
    int cnt = 0;
    #pragma unroll 4
    for (int it = 0; it < NN / 128; it++) {
        float4 v = __ldcs(&row4[it * 32 + lane]);
        int jb = it * 128 + lane * 4;
        bool n0 = (v.x != 0.f) || (jb     == i);
        bool n1 = (v.y != 0.f) || (jb + 1 == i);
        bool n2 = (v.z != 0.f) || (jb + 2 == i);
        bool n3 = (v.w != 0.f) || (jb + 3 == i);
        unsigned m0 = __ballot_sync(0xffffffffu, n0);
        unsigned m1 = __ballot_sync(0xffffffffu, n1);
        unsigned m2 = __ballot_sync(0xffffffffu, n2);
        unsigned m3 = __ballot_sync(0xffffffffu, n3);
        int p = cnt + __popc(m0 & bm) + __popc(m1 & bm) + __popc(m2 & bm) + __popc(m3 & bm);
        if (n0) { if (p < ELL_S) crow[p] = jb;     p++; }
        if (n1) { if (p < ELL_S) crow[p] = jb + 1; p++; }
        if (n2) { if (p < ELL_S) crow[p] = jb + 2; p++; }
        if (n3) { if (p < ELL_S) crow[p] = jb + 3; p++; }
        cnt += __popc(m0) + __popc(m1) + __popc(m2) + __popc(m3);
    }
    if (cnt > ELL_S) cnt = ELL_S;
    if (lane == 0) {
        g_cnt[warp] = cnt;
        g_d[warp] = rsqrtf((float)cnt);   // rowsum == cnt (entries exactly 1.0), cnt>=1
    }
}

// K1b: fused prep — blocks [0,2048): dw[row][s] = d[r,col]; blocks [2048,2080): What.
__global__ void k_prep(const float* __restrict__ W) {
    int b = blockIdx.x;
    if (b < 2048) {
        int row = b * 8 + (threadIdx.x >> 5);
        int lane = threadIdx.x & 31;
        int rbase = row & ~(NN - 1);
        int cnt = g_cnt[row];
        const int* crow = g_cols + (size_t)row * ELL_S;
        float* dwr = g_dw + (size_t)row * ELL_S;
        for (int s = lane; s < cnt; s += 32) dwr[s] = g_d[rbase + crow[s]];
    } else {
        int idx = (b - 2048) * 256 + threadIdx.x;   // < LLAY*HH*HH = 8192
        const float* p = W + (size_t)idx * RR;
        float w0 = p[0], w1 = p[1], w2 = p[2], w3 = p[3];
        int l = idx >> 12, q = idx & 4095;
        float* base = g_What + (size_t)l * 3 * HH * HH;
        base[q]           = w0 + w1 + w2 + w3;
        base[HH*HH + q]   = w0 - w2;
        base[2*HH*HH + q] = w0 - w1 + w2 - w3;
    }
}

// K2: Y[r,j,:] = d_rj * (X[j,:] @ W1[r]).  32 rows/block, grid 512.
__global__ void __launch_bounds__(256) k_xw1(const float* __restrict__ X,
                                             const float* __restrict__ W1) {
    extern __shared__ float dsm[];
    float* sW = dsm;                 // FINN*HH = 32KB
    float* sX = dsm + FINN * HH;     // 32*FINN = 16KB
    int r = blockIdx.y, i0 = blockIdx.x * 32, tid = threadIdx.x;
    const float4* wg4 = (const float4*)(W1 + (size_t)r * FINN * HH);
    float4* sW4 = (float4*)sW;
    for (int q = tid; q < FINN * HH / 4; q += 256) sW4[q] = wg4[q];
    const float4* xg4 = (const float4*)(X + (size_t)i0 * FINN);
    float4* sX4 = (float4*)sX;
    for (int q = tid; q < 32 * FINN / 4; q += 256) sX4[q] = xg4[q];
    __syncthreads();
    int h = tid & 63, rg = tid >> 6;
    const float* sXb = sX + rg * 8 * FINN;
    float acc[8];
    #pragma unroll
    for (int rr = 0; rr < 8; rr++) acc[rr] = 0.f;
    for (int f = 0; f < FINN; f += 4) {
        float w0 = sW[f*64+h], w1 = sW[(f+1)*64+h], w2 = sW[(f+2)*64+h], w3 = sW[(f+3)*64+h];
        #pragma unroll
        for (int rr = 0; rr < 8; rr++) {
            float4 x = *(const float4*)&sXb[rr * FINN + f];
            acc[rr] += x.x*w0 + x.y*w1 + x.z*w2 + x.w*w3;
        }
    }
    #pragma unroll
    for (int rr = 0; rr < 8; rr++) {
        int gi = (r << 12) + i0 + rg * 8 + rr;
        g_Y[(size_t)gi * HH + h] = g_d[gi] * acc[rr];
    }
}

// K4a: Y[r,j,:] = d_rj * (h[r,j,:] @ W2[r]).  32 rows/block, grid 512.
__global__ void __launch_bounds__(256) k_hw2(const float* __restrict__ W2) {
    __shared__ float sW[HH * HH];    // 16KB
    __shared__ float sX[32 * HH];    // 8KB
    int r = blockIdx.y, i0 = blockIdx.x * 32, tid = threadIdx.x;
    const float4* wg4 = (const float4*)(W2 + (size_t)r * HH * HH);
    float4* sW4 = (float4*)sW;
    for (int q = tid; q < HH * HH / 4; q += 256) sW4[q] = wg4[q];
    const float4* hg4 = (const float4*)(g_h + ((size_t)((r << 12) + i0)) * HH);
    float4* sX4 = (float4*)sX;
    for (int q = tid; q < 32 * HH / 4; q += 256) sX4[q] = hg4[q];
    __syncthreads();
    int h = tid & 63, rg = tid >> 6;
    const float* sXb = sX + rg * 8 * HH;
    float acc[8];
    #pragma unroll
    for (int rr = 0; rr < 8; rr++) acc[rr] = 0.f;
    for (int f = 0; f < HH; f += 4) {
        float w0 = sW[f*64+h], w1 = sW[(f+1)*64+h], w2 = sW[(f+2)*64+h], w3 = sW[(f+3)*64+h];
        #pragma unroll
        for (int rr = 0; rr < 8; rr++) {
            float4 x = *(const float4*)&sXb[rr * HH + f];
            acc[rr] += x.x*w0 + x.y*w1 + x.z*w2 + x.w*w3;
        }
    }
    #pragma unroll
    for (int rr = 0; rr < 8; rr++) {
        int gi = (r << 12) + i0 + rg * 8 + rr;
        g_Y[(size_t)gi * HH + h] = g_d[gi] * acc[rr];
    }
}

// K3: first GCN aggregation, warp per row (8 rows/block), float2 gathers.
__global__ void __launch_bounds__(256) k_spmm_gcn(const float* __restrict__ bias) {
    int row = blockIdx.x * 8 + (threadIdx.x >> 5);
    int lane = threadIdx.x & 31;
    int r = row >> 12;
    int cnt = g_cnt[row];
    const int* crow = g_cols + (size_t)row * ELL_S;
    const float2* Y2 = (const float2*)g_Y + (((size_t)r) << 12) * 32;   // relation base
    float ax = 0.f, ay = 0.f;
    int s = 0;
    for (; s + 8 <= cnt; s += 8) {
        int j[8];
        #pragma unroll
        for (int u = 0; u < 8; u++) j[u] = crow[s + u];
        #pragma unroll
        for (int u = 0; u < 8; u++) {
            float2 f = Y2[(size_t)j[u] * 32 + lane];
            ax += f.x; ay += f.y;
        }
    }
    for (; s < cnt; s++) {
        float2 f = Y2[(size_t)crow[s] * 32 + lane];
        ax += f.x; ay += f.y;
    }
    float di = g_d[row];
    float vx = di * ax + bias[r * HH + 2 * lane];
    float vy = di * ay + bias[r * HH + 2 * lane + 1];
    float2 out; out.x = vx > 0.f ? vx : 0.f; out.y = vy > 0.f ? vy : 0.f;
    ((float2*)g_h)[(size_t)row * 32 + lane] = out;
}

// K4b: second GCN aggregation, warp per (node,relation), 2 nodes/block,
// fused frequency-plane packing epilogue into plane buffer 0.
__global__ void __launch_bounds__(256) k_spmm_xhat(const float* __restrict__ bias) {
    __shared__ float2 sh[2][4][32];
    int tid = threadIdx.x;
    int wid = tid >> 5, lane = tid & 31;
    int nl = wid >> 2, r = wid & 3;
    int i = blockIdx.x * 2 + nl;
    int row = (r << 12) + i;
    int cnt = g_cnt[row];
    const int* crow = g_cols + (size_t)row * ELL_S;
    const float2* Y2 = (const float2*)g_Y + (((size_t)r) << 12) * 32;   // relation base
    float ax = 0.f, ay = 0.f;
    int s = 0;
    for (; s + 8 <= cnt; s += 8) {
        int j[8];
        #pragma unroll
        for (int u = 0; u < 8; u++) j[u] = crow[s + u];
        #pragma unroll
        for (int u = 0; u < 8; u++) {
            float2 f = Y2[(size_t)j[u] * 32 + lane];
            ax += f.x; ay += f.y;
        }
    }
    for (; s < cnt; s++) {
        float2 f = Y2[(size_t)crow[s] * 32 + lane];
        ax += f.x; ay += f.y;
    }
    float di = g_d[row];
    float vx = di * ax + bias[r * HH + 2 * lane];
    float vy = di * ay + bias[r * HH + 2 * lane + 1];
    float2 v; v.x = vx > 0.f ? vx : 0.f; v.y = vy > 0.f ? vy : 0.f;
    sh[nl][r][lane] = v;
    __syncthreads();
    if (r == 0) {   // warps 0 and 4: plane epilogue for their node
        float2 x0 = sh[nl][0][lane], x1 = sh[nl][1][lane];
        float2 x2 = sh[nl][2][lane], x3 = sh[nl][3][lane];
        int f0 = 2 * lane, f1 = 2 * lane + 1;
        g_X02[0][(size_t)i * 128 + f0]      = x0.x + x1.x + x2.x + x3.x;  // plane0
        g_X02[0][(size_t)i * 128 + f1]      = x0.y + x1.y + x2.y + x3.y;
        g_X02[0][(size_t)i * 128 + 64 + f0] = x0.x - x1.x + x2.x - x3.x;  // plane2
        g_X02[0][(size_t)i * 128 + 64 + f1] = x0.y - x1.y + x2.y - x3.y;
        g_X1 [0][(size_t)i * 64 + f0]       = x0.x - x2.x;                // plane1
        g_X1 [0][(size_t)i * 64 + f1]       = x0.y - x2.y;
    }
}

// Fused MRGCO layer: Chat gather (640 threads), Ohat, Dhat (192 threads, What
// via L1), final ifft + relu -> tX + next-layer planes. Reads plane buffer
// [src], writes [src^1] (ping-pong: avoids cross-block read/write race).
__global__ void __launch_bounds__(640) k_mrgco(int layer, int write_next, int src) {
    __shared__ float part [4][128];
    __shared__ float part1[2][64];
    __shared__ float sO[3][HH];
    __shared__ float sD[3][HH];
    int i = blockIdx.x, tid = threadIdx.x;
    const float* X02s = g_X02[src];
    const float* X1s  = g_X1[src];
    if (tid < 512) {
        int r = tid >> 7, hh = tid & 127;
        int row = (r << 12) + i;
        int cnt = g_cnt[row];
        const int*   crow = g_cols + (size_t)row * ELL_S;
        const float* dwr  = g_dw   + (size_t)row * ELL_S;
        float s = 0.f;
        int ss = 0;
        for (; ss + 8 <= cnt; ss += 8) {
            int j[8]; float w[8];
            #pragma unroll
            for (int u = 0; u < 8; u++) { j[u] = crow[ss+u]; w[u] = dwr[ss+u]; }
            #pragma unroll
            for (int u = 0; u < 8; u++) s += w[u] * X02s[(size_t)j[u] * 128 + hh];
        }
        for (; ss < cnt; ss++) s += dwr[ss] * X02s[(size_t)crow[ss] * 128 + hh];
        float coef = (hh < 64) ? 1.f : ((r & 1) ? -1.f : 1.f);   // Mc[0][r] / Mc[2][r]
        part[r][hh] = coef * g_d[row] * s;
    } else {
        int t2 = tid - 512;
        int rr = t2 >> 6, h = t2 & 63;
        int r = rr * 2;                                          // relations 0, 2
        int row = (r << 12) + i;
        int cnt = g_cnt[row];
        const int*   crow = g_cols + (size_t)row * ELL_S;
        const float* dwr  = g_dw   + (size_t)row * ELL_S;
        float s = 0.f;
        int ss = 0;
        for (; ss + 8 <= cnt; ss += 8) {
            int j[8]; float w[8];
            #pragma unroll
            for (int u = 0; u < 8; u++) { j[u] = crow[ss+u]; w[u] = dwr[ss+u]; }
            #pragma unroll
            for (int u = 0; u < 8; u++) s += w[u] * X1s[(size_t)j[u] * 64 + h];
        }
        for (; ss < cnt; ss++) s += dwr[ss] * X1s[(size_t)crow[ss] * 64 + h];
        part1[rr][h] = (rr ? -1.f : 1.f) * g_d[row] * s;         // Mc[1][0]=+1, Mc[1][2]=-1
    }
    __syncthreads();
    if (tid < HH) {
        float C0 = part[0][tid] + part[1][tid] + part[2][tid] + part[3][tid];
        float C2 = part[0][64+tid] + part[1][64+tid] + part[2][64+tid] + part[3][64+tid];
        float C1 = part1[0][tid] + part1[1][tid];
        float O0 = 0.25f * (C0 + 2.f*C1 + C2);
        float O1 = 0.25f * (C0 - C2);
        float O2 = 0.25f * (C0 - 2.f*C1 + C2);
        float O3 = O1;
        sO[0][tid] = O0 + O1 + O2 + O3;     // Ohat planes
        sO[1][tid] = O0 - O2;
        sO[2][tid] = O0 - O1 + O2 - O3;
    }
    __syncthreads();
    if (tid < 192) {
        int k = tid >> 6, l = tid & 63;
        const float* wk = g_What + (size_t)layer * 3 * HH * HH + (size_t)k * HH * HH;
        float acc = 0.f;
        #pragma unroll 8
        for (int j = 0; j < HH; j++)
            acc += sO[k][j] * __ldg(&wk[j * HH + l]);
        sD[k][l] = acc;
    }
    __syncthreads();
    if (tid < HH) {
        float D0 = sD[0][tid], D1 = sD[1][tid], D2 = sD[2][tid];
        float v0 = 0.25f * (D0 + 2.f*D1 + D2);
        float v1 = 0.25f * (D0 - D2);
        float v2 = 0.25f * (D0 - 2.f*D1 + D2);
        float v3 = v1;
        v0 = v0 > 0.f ? v0 : 0.f;  v1 = v1 > 0.f ? v1 : 0.f;
        v2 = v2 > 0.f ? v2 : 0.f;  v3 = v3 > 0.f ? v3 : 0.f;
        float4 tv; tv.x = v0; tv.y = v1; tv.z = v2; tv.w = v3;
        *(float4*)&g_tX[((size_t)i * HH + tid) * RR] = tv;
        if (write_next) {
            int dst = src ^ 1;
            g_X02[dst][(size_t)i * 128 + tid]      = v0 + v1 + v2 + v3;
            g_X02[dst][(size_t)i * 128 + 64 + tid] = v0 - v1 + v2 - v3;
            g_X1 [dst][(size_t)i * 64 + tid]       = v0 - v2;
        }
    }
}

// Head: 4 targets per block (grid 128), lin1_w cached in smem.
__global__ void k_head(const int* __restrict__ target_x, const int* __restrict__ target,
                       const float* __restrict__ l1w, const float* __restrict__ l1b,
                       const float* __restrict__ l2w, const float* __restrict__ l2b,
                       float* __restrict__ y_out) {
    extern __shared__ float dsm[];
    float* sw1 = dsm;                // 256*64 = 64KB
    float* sf  = sw1 + 256 * HH;     // 256
    float* sp  = sf + 256;           // 4*64
    float* szz = sp + 256;           // 64
    float* sy  = szz + 64;           // 16
    int tid = threadIdx.x;
    {
        const float4* w4 = (const float4*)l1w;
        float4* s4 = (float4*)sw1;
        for (int q = tid; q < 256 * HH / 4; q += 256) s4[q] = w4[q];
    }
    int h = tid & 63, part = tid >> 6;
    for (int tt = 0; tt < 4; tt++) {
        int t = blockIdx.x * 4 + tt;
        __syncthreads();
        int n = target_x[t];
        sf[tid] = g_tX[(size_t)n * 256 + tid];
        __syncthreads();
        float acc = 0.f;
        #pragma unroll 8
        for (int q = part * 64; q < part * 64 + 64; q++)
            acc += sf[q] * sw1[q * 64 + h];
        sp[part * 64 + h] = acc;
        __syncthreads();
        if (tid < HH) {
            float z = sp[tid] + sp[64 + tid] + sp[128 + tid] + sp[192 + tid] + l1b[tid];
            szz[tid] = z > 0.f ? z : 0.f;
        }
        __syncthreads();
        if (tid < CC) {
            float yv = l2b[tid];
            #pragma unroll 8
            for (int hh = 0; hh < HH; hh++) yv += szz[hh] * l2w[hh * CC + tid];
            sy[tid] = yv;
            y_out[t * CC + tid] = yv;
        }
        __syncthreads();
        if (tid == 0) {
            float mx = sy[0];
            for (int c = 1; c < CC; c++) mx = fmaxf(mx, sy[c]);
            float se = 0.f;
            for (int c = 0; c < CC; c++) se += expf(sy[c] - mx);
            g_losses[t] = mx + logf(se) - sy[target[t]];
        }
    }
}

__global__ void k_loss_reduce(float* __restrict__ loss_ptr) {
    __shared__ float s[256];
    int tid = threadIdx.x;
    s[tid] = g_losses[tid] + g_losses[tid + 256];
    __syncthreads();
    for (int o = 128; o > 0; o >>= 1) {
        if (tid < o) s[tid] += s[tid + o];
        __syncthreads();
    }
    if (tid == 0) *loss_ptr = s[0] / (float)TT;
}

extern "C" void kernel_launch(void* const* d_in, const int* in_sizes, int n_in,
                              void* d_out, int out_size) {
    const float* A        = (const float*)d_in[0];
    const float* X        = (const float*)d_in[1];
    const int*   target_x = (const int*)  d_in[2];
    const int*   target   = (const int*)  d_in[3];
    const float* gw1      = (const float*)d_in[4];
    const float* gb1      = (const float*)d_in[5];
    const float* gw2      = (const float*)d_in[6];
    const float* gb2      = (const float*)d_in[7];
    const float* mw       = (const float*)d_in[8];
    const float* l1w      = (const float*)d_in[9];
    const float* l1b      = (const float*)d_in[10];
    const float* l2w      = (const float*)d_in[11];
    const float* l2b      = (const float*)d_in[12];

    float* outf = (float*)d_out;
    float* loss_ptr = nullptr;
    float* y_dst;
    if (out_size >= TT * CC + 1)  { loss_ptr = outf; y_dst = outf + 1; }
    else if (out_size >= TT * CC) { y_dst = outf; }
    else {
        loss_ptr = outf;
        void* p = nullptr; cudaGetSymbolAddress(&p, g_yscratch);
        y_dst = (float*)p;
    }

    const int XW1_SMEM  = (FINN * HH + 32 * FINN) * 4;              // 48 KB
    const int HEAD_SMEM = (256 * HH + 256 + 256 + 64 + 16) * 4;     // ~66 KB
    cudaFuncSetAttribute(k_xw1,  cudaFuncAttributeMaxDynamicSharedMemorySize, XW1_SMEM);
    cudaFuncSetAttribute(k_head, cudaFuncAttributeMaxDynamicSharedMemorySize, HEAD_SMEM);

    // 1) sparsity pattern + degrees (single DRAM pass over A), then prep
    k_build<<<RR * NN / 8, 256>>>(A);
    k_prep<<<2048 + LLAY * HH * HH / 256, 256>>>(mw);

    // 2) per-relation GCN x2
    k_xw1<<<dim3(NN / 32, RR), 256, XW1_SMEM>>>(X, gw1);
    k_spmm_gcn<<<RR * NN / 8, 256>>>(gb1);
    k_hw2<<<dim3(NN / 32, RR), 256>>>(gw2);
    k_spmm_xhat<<<NN / 2, 256>>>(gb2);   // fused plane packing into buffer 0

    // 3) MRGCO layers (ping-pong plane buffers across layers)
    for (int l = 0; l < LLAY; l++)
        k_mrgco<<<NN, 640>>>(l, l + 1 < LLAY, l & 1);

    // 4) head + deterministic loss reduction
    k_head<<<TT / 4, 256, HEAD_SMEM>>>(target_x, target, l1w, l1b, l2w, l2b, y_dst);
    if (loss_ptr) k_loss_reduce<<<1, 256>>>(loss_ptr);
}